// round 8
// baseline (speedup 1.0000x reference)
#include <cuda_runtime.h>

#define NN 64
#define NMAT 4096
#define WPB 2                 // warps (=matrices) per block
#define GRID (NMAT / WPB)     // 2048 blocks
#define ITERS 4               // + folded rowsum init = 5 applications

__device__ float g_acc[NN];
__device__ unsigned int g_ticket;

typedef unsigned long long u64;

__device__ __forceinline__ u64 ffma2(u64 a, u64 b, u64 c) {
    u64 d;
    asm("fma.rn.f32x2 %0, %1, %2, %3;" : "=l"(d) : "l"(a), "l"(b), "l"(c));
    return d;
}
__device__ __forceinline__ u64 fadd2(u64 a, u64 b) {
    u64 d;
    asm("add.rn.f32x2 %0, %1, %2;" : "=l"(d) : "l"(a), "l"(b));
    return d;
}
// XOR swizzle on 16B-chunk index: conflict-free for BOTH the coalesced
// store pattern (c = i*32+lane) and the per-row load pattern (c = lane*32+i).
__device__ __forceinline__ int sw(int c) { return c ^ ((c >> 5) & 7); }

// One warp per matrix. Lane j owns rows 2j,2j+1 (in regs, f32x2-packed) and
// the v-pair (v[2j],v[2j+1]). Matvec = 32 shfl-broadcasts + 64 FFMA2, no
// cross-lane reduction, no barriers, no per-iteration shared memory.
__global__ __launch_bounds__(WPB * 32, 6)
void power_kernel(const float* __restrict__ x,
                  const float* __restrict__ wt,
                  const float* __restrict__ rc,
                  float* __restrict__ out)
{
    const int lane = threadIdx.x & 31;
    const int wid  = threadIdx.x >> 5;
    const int b    = blockIdx.x * WPB + wid;
    const float* M = rc + (size_t)b * (NN * NN);

    __shared__ __align__(16) float4 stage[WPB][1024];   // 16KB per warp

    // Coalesced load -> swizzled stage (quarter-warps hit full 128B lines).
#pragma unroll
    for (int i = 0; i < 32; ++i) {
        const int c = i * 32 + lane;
        stage[wid][sw(c)] = reinterpret_cast<const float4*>(M)[c];
    }
    __syncwarp();

    // Lane j's two rows: chunks [j*32, j*32+16) = row 2j, [+16,+32) = row 2j+1.
    u64 re[32], ro[32];
#pragma unroll
    for (int ii = 0; ii < 16; ++ii) {
        const int ce = lane * 32 + ii;
        const int co = ce + 16;
        float4 de = stage[wid][sw(ce)];
        float4 dd = stage[wid][sw(co)];
        ulonglong2 ue = *reinterpret_cast<ulonglong2*>(&de);
        ulonglong2 uo = *reinterpret_cast<ulonglong2*>(&dd);
        re[2 * ii] = ue.x;  re[2 * ii + 1] = ue.y;
        ro[2 * ii] = uo.x;  ro[2 * ii + 1] = uo.y;
    }

    // v0 = M * ones = rowsums (scale of v is irrelevant: output uses v[n]/v[s]).
    u64 v2;
    {
        u64 e0 = 0, e1 = 0, o0 = 0, o1 = 0;
#pragma unroll
        for (int p = 0; p < 32; p += 2) {
            e0 = fadd2(e0, re[p]);  e1 = fadd2(e1, re[p + 1]);
            o0 = fadd2(o0, ro[p]);  o1 = fadd2(o1, ro[p + 1]);
        }
        u64 se = fadd2(e0, e1), so = fadd2(o0, o1);
        float2 fe = *reinterpret_cast<float2*>(&se);
        float2 fo = *reinterpret_cast<float2*>(&so);
        float2 nv = make_float2(fe.x + fe.y, fo.x + fo.y);
        v2 = *reinterpret_cast<u64*>(&nv);
    }

    // Power iterations: lane-local rows, v broadcast by shfl.
#pragma unroll
    for (int it = 0; it < ITERS; ++it) {
        u64 ae0 = 0, ae1 = 0, ao0 = 0, ao1 = 0;
#pragma unroll
        for (int p = 0; p < 32; ++p) {
            const u64 vv = __shfl_sync(0xffffffffu, v2, p);
            if (p & 1) { ae1 = ffma2(re[p], vv, ae1); ao1 = ffma2(ro[p], vv, ao1); }
            else       { ae0 = ffma2(re[p], vv, ae0); ao0 = ffma2(ro[p], vv, ao0); }
        }
        u64 se = fadd2(ae0, ae1), so = fadd2(ao0, ao1);
        float2 fe = *reinterpret_cast<float2*>(&se);
        float2 fo = *reinterpret_cast<float2*>(&so);
        float2 nv = make_float2(fe.x + fe.y, fo.x + fo.y);
        v2 = *reinterpret_cast<u64*>(&nv);
    }

    // Epilogue: coef = x*wt*M[s][s] / v[s]; accumulate coef*v.
    {
        const float2 vf = *reinterpret_cast<const float2*>(&v2);
        const int s = b >> 6;
        const float vs_lo = __shfl_sync(0xffffffffu, vf.x, s >> 1);
        const float vs_hi = __shfl_sync(0xffffffffu, vf.y, s >> 1);
        const float vs = (s & 1) ? vs_hi : vs_lo;

        const int cd = (s * NN + s) >> 2;          // 16B chunk of M[s][s]
        float4 dch = stage[wid][sw(cd)];
        const float mss = ((s & 3) == 0) ? dch.x : ((s & 3) == 1) ? dch.y
                        : ((s & 3) == 2) ? dch.z : dch.w;

        const float coef = x[b] * wt[b] * mss / vs;
        atomicAdd(&g_acc[2 * lane],     coef * vf.x);
        atomicAdd(&g_acc[2 * lane + 1], coef * vf.y);
    }

    // Last block drains g_acc -> out and resets scratch (graph-replay safe).
    __threadfence();
    __shared__ int is_last;
    if (threadIdx.x == 0)
        is_last = (atomicAdd(&g_ticket, 1u) == (unsigned)(GRID - 1));
    __syncthreads();
    if (is_last) {
        if (threadIdx.x < NN) {
            out[threadIdx.x] = g_acc[threadIdx.x];
            g_acc[threadIdx.x] = 0.0f;
        }
        if (threadIdx.x == 0) g_ticket = 0u;
    }
}

extern "C" void kernel_launch(void* const* d_in, const int* in_sizes, int n_in,
                              void* d_out, int out_size)
{
    // inputs: x, weights_t, weights_r (unused), r_zeros (all-zero), r_const
    const float* x  = (const float*)d_in[0];
    const float* wt = (const float*)d_in[1];
    const float* rc = (const float*)d_in[4];

    power_kernel<<<GRID, WPB * 32>>>(x, wt, rc, (float*)d_out);
}

// round 9
// speedup vs baseline: 1.8438x; 1.8438x over previous
#include <cuda_runtime.h>
#include <cstdint>

#define NN 64
#define NMAT 4096
#define G 4                    // matrices per block, cp.async pipelined
#define GRID (NMAT / G)        // 1024 blocks
#define VAPPS 4                // + rowsum init = 5 applications total
#define RP 68                  // smem row pitch (words): bank-staggered rows

__device__ float g_acc[NN];
__device__ unsigned int g_ticket;

typedef unsigned long long u64;

__device__ __forceinline__ u64 ffma2(u64 a, u64 b, u64 c) {
    u64 d;
    asm("fma.rn.f32x2 %0, %1, %2, %3;" : "=l"(d) : "l"(a), "l"(b), "l"(c));
    return d;
}
__device__ __forceinline__ u64 fadd2(u64 a, u64 b) {
    u64 d;
    asm("add.rn.f32x2 %0, %1, %2;" : "=l"(d) : "l"(a), "l"(b));
    return d;
}
__device__ __forceinline__ void cp16(uint32_t dst, const void* src) {
    asm volatile("cp.async.cg.shared.global [%0], [%1], 16;" :: "r"(dst), "l"(src));
}

// Stream one 16KB matrix into a pitched smem tile. Coalesced gmem (chunk
// c = i*256+t), conflict-free smem writes (bank = 4*((r + j) mod 8), r fixed
// per phase, j consecutive).
__device__ __forceinline__ void issue_tile(float* bufp, const float* M, int t) {
    uint32_t b32 = (uint32_t)__cvta_generic_to_shared(bufp);
    const float4* src = reinterpret_cast<const float4*>(M);
#pragma unroll
    for (int i = 0; i < 4; ++i) {
        const int c = i * 256 + t;          // 16B-chunk index 0..1023
        const int r = c >> 4, j = c & 15;   // row, chunk-in-row
        cp16(b32 + (uint32_t)(r * RP + j * 4) * 4u, src + c);
    }
}

// 256 threads: k = t&63 (row), q = t>>6 (quarter). Warp = 32 consecutive rows
// of ONE quarter -> v reads are uniform broadcasts, row LDS conflict-free via
// pitch 68. Matrices pipelined through 2 smem buffers via cp.async.
__global__ __launch_bounds__(256, 5)
void power_kernel(const float* __restrict__ x,
                  const float* __restrict__ wt,
                  const float* __restrict__ rc,
                  float* __restrict__ out)
{
    const int t = threadIdx.x;
    const int k = t & 63;
    const int q = t >> 6;
    const int base = (int)blockIdx.x * G;

    __shared__ __align__(16) float buf[2][NN * RP];   // 2 x 17408 B
    __shared__ __align__(16) float part[4 * RP];      // quarter partials
    __shared__ __align__(16) float vbuf[RP];
    __shared__ int is_last;

    issue_tile(buf[0], rc + (size_t)base * NN * NN, t);
    asm volatile("cp.async.commit_group;" ::: "memory");
    issue_tile(buf[1], rc + (size_t)(base + 1) * NN * NN, t);
    asm volatile("cp.async.commit_group;" ::: "memory");

#pragma unroll 1
    for (int g = 0; g < G; ++g) {
        const int b = base + g;
        const int s = b >> 6;
        // groups committed so far = 2+g; leaving <=1 pending completes group g.
        asm volatile("cp.async.wait_group 1;" ::: "memory");
        __syncthreads();   // buf[g&1] visible to all; prev part-reads done

        // Uniform scalars issued early (latency hidden under the matvecs).
        const float mss = __ldg(rc + (size_t)b * NN * NN + s * NN + s);
        const float xw  = __ldg(x + b) * __ldg(wt + b);

        // Row quarter -> regs: words [16q, 16q+16) of pitched row k.
        u64 row[8];
        const float* bp = &buf[g & 1][k * RP + 16 * q];
#pragma unroll
        for (int i = 0; i < 4; ++i) {
            float4 f = *reinterpret_cast<const float4*>(bp + 4 * i);
            row[2 * i]     = *reinterpret_cast<u64*>(&f.x);
            row[2 * i + 1] = *reinterpret_cast<u64*>(&f.z);
        }

        // Application 0: v = M*ones -> quarter rowsum from regs.
        {
            u64 s0 = fadd2(fadd2(row[0], row[1]), fadd2(row[2], row[3]));
            u64 s1 = fadd2(fadd2(row[4], row[5]), fadd2(row[6], row[7]));
            u64 ss = fadd2(s0, s1);
            float2 f = *reinterpret_cast<float2*>(&ss);
            part[q * RP + k] = f.x + f.y;
        }
        __syncthreads();   // buf consumed by all + partials visible

        // Prefetch matrix g+2 into the buffer we just freed.
        if (g + 2 < G)
            issue_tile(buf[g & 1], rc + (size_t)(b + 2) * NN * NN, t);
        asm volatile("cp.async.commit_group;" ::: "memory");

        float vk = part[k] + part[RP + k] + part[2 * RP + k] + part[3 * RP + k];
        if (q == 0) vbuf[k] = vk;
        __syncthreads();

#pragma unroll
        for (int it = 0; it < VAPPS; ++it) {
            u64 a0 = 0, a1 = 0, a2 = 0, a3 = 0;
#pragma unroll
            for (int i = 0; i < 4; ++i) {
                // uniform per-warp address -> broadcast, conflict-free
                float4 f = *reinterpret_cast<const float4*>(&vbuf[16 * q + 4 * i]);
                u64 vx = *reinterpret_cast<u64*>(&f.x);
                u64 vy = *reinterpret_cast<u64*>(&f.z);
                if (i & 1) { a2 = ffma2(row[2*i], vx, a2); a3 = ffma2(row[2*i+1], vy, a3); }
                else       { a0 = ffma2(row[2*i], vx, a0); a1 = ffma2(row[2*i+1], vy, a1); }
            }
            u64 ss = fadd2(fadd2(a0, a2), fadd2(a1, a3));
            float2 f = *reinterpret_cast<float2*>(&ss);
            part[q * RP + k] = f.x + f.y;
            __syncthreads();
            vk = part[k] + part[RP + k] + part[2 * RP + k] + part[3 * RP + k];
            if (it < VAPPS - 1) {
                if (q == 0) vbuf[k] = vk;
                __syncthreads();
            }
        }

        // Epilogue: v[s] via uniform reads; q==0 lanes emit the 64 atomics.
        const float vs = part[s] + part[RP + s] + part[2 * RP + s] + part[3 * RP + s];
        if (q == 0) {
            const float coef = xw * mss / vs;
            atomicAdd(&g_acc[k], coef * vk);
        }
    }

    // Last block drains g_acc -> out and resets scratch (graph-replay safe).
    __threadfence();
    if (t == 0)
        is_last = (atomicAdd(&g_ticket, 1u) == (unsigned)(GRID - 1));
    __syncthreads();
    if (is_last) {
        if (t < NN) { out[t] = g_acc[t]; g_acc[t] = 0.0f; }
        if (t == 0) g_ticket = 0u;
    }
}

extern "C" void kernel_launch(void* const* d_in, const int* in_sizes, int n_in,
                              void* d_out, int out_size)
{
    // inputs: x, weights_t, weights_r (unused), r_zeros (all-zero), r_const
    const float* x  = (const float*)d_in[0];
    const float* wt = (const float*)d_in[1];
    const float* rc = (const float*)d_in[4];

    // Hint max smem carveout so 5 blocks/SM fit (36.2KB static each).
    static bool carveout_set = false;
    if (!carveout_set) {
        cudaFuncSetAttribute(power_kernel,
                             cudaFuncAttributePreferredSharedMemoryCarveout, 100);
        carveout_set = true;
    }
    power_kernel<<<GRID, 256>>>(x, wt, rc, (float*)d_out);
}